// round 14
// baseline (speedup 1.0000x reference)
#include <cuda_runtime.h>
#include <mma.h>
#include <cstdint>
#include <cstddef>

using namespace nvcuda;

// ---------------- problem constants ----------------
#define NUM_HEADS 8
#define DHEAD 32
#define BLOCK_SZ 8
#define HALO 3
#define WIN 14
#define WINP 196
#define NHB 12
#define NB 144
#define HW 96
#define SPATIAL 9216
#define BATCH 8
#define CIN 256
#define OQKV 768
#define SCALE 0.17677669529663687f
#define LOG2E 1.4426950408889634f

typedef unsigned long long u64;

// ---- f32x2 packed-math helpers ----
__device__ __forceinline__ u64 pack2(float lo, float hi) {
    u64 r; asm("mov.b64 %0, {%1, %2};" : "=l"(r) : "f"(lo), "f"(hi)); return r;
}
__device__ __forceinline__ void unpack2(u64 v, float& lo, float& hi) {
    asm("mov.b64 {%0, %1}, %2;" : "=f"(lo), "=f"(hi) : "l"(v));
}
__device__ __forceinline__ void fma2(u64& d, u64 a, u64 b) {
    asm("fma.rn.f32x2 %0, %1, %2, %0;" : "+l"(d) : "l"(a), "l"(b));
}
__device__ __forceinline__ void mul2(u64& d, u64 a) {
    asm("mul.rn.f32x2 %0, %0, %1;" : "+l"(d) : "l"(a));
}
__device__ __forceinline__ u64 add2(u64 a, u64 b) {
    u64 r; asm("add.rn.f32x2 %0, %1, %2;" : "=l"(r) : "l"(a), "l"(b)); return r;
}
__device__ __forceinline__ unsigned smem_u32(const void* p) {
    unsigned a;
    asm("{ .reg .u64 t; cvta.to.shared.u64 t, %1; cvt.u32.u64 %0, t; }"
        : "=r"(a) : "l"(p));
    return a;
}
#define CP_ASYNC16(dst_u32, src) \
    asm volatile("cp.async.cg.shared.global [%0], [%1], 16;" :: "r"(dst_u32), "l"(src))
#define CP_COMMIT() asm volatile("cp.async.commit_group;")
#define CP_WAIT1()  asm volatile("cp.async.wait_group 1;" ::: "memory")

// scratch — attention-friendly layouts
__device__ float g_wt[(size_t)CIN * OQKV];                              // W^T [k][o]
__device__ float g_qT[(size_t)BATCH * NUM_HEADS * SPATIAL * DHEAD];     // [b][h][s][32]
__device__ float g_kvT[(size_t)BATCH * NUM_HEADS * SPATIAL * 64];       // [b][h][s][64]

// ---------------- kernel 0: weight transpose ----------------
__global__ void __launch_bounds__(1024) wt_kernel(
    const float* __restrict__ qw, const float* __restrict__ kvw)
{
    __shared__ float t[32][33];
    const int o0 = blockIdx.x * 32;
    const int k0 = blockIdx.y * 32;
    const int o = o0 + threadIdx.y;
    const int k = k0 + threadIdx.x;
    const float* src = (o < 256) ? (qw + (size_t)o * CIN) : (kvw + (size_t)(o - 256) * CIN);
    t[threadIdx.y][threadIdx.x] = src[k];
    __syncthreads();
    g_wt[(size_t)(k0 + threadIdx.y) * OQKV + o0 + threadIdx.x] = t[threadIdx.x][threadIdx.y];
}

// ---------------- kernel 1: QKV GEMM — tf32 wmma (tf32x3 compensated) --------
// C[o][s] = sum_k Wt[k][o] * x[b][k][s].  CTA tile 128(o) x 128(s), BK=16,
// 256 threads = 8 warps in 2(M) x 4(N); warp tile 64x32 (4x2 m16n16k8 frags).
// cp.async 3-stage pipeline identical to the proven FFMA2 version.
#define GBK 16
#define ASTR 132                        // smem row stride (floats)
#define STG_FLOATS (GBK * ASTR)         // per stage per matrix
#define GEMM_SMEM (3 * 2 * STG_FLOATS * 4)   // 50688 B
#define NT (CIN / GBK)                  // 16 tiles

__global__ void __launch_bounds__(256) qkv_gemm(const float* __restrict__ x)
{
    extern __shared__ float dsm[];
    float* sA = dsm;                    // [3][16][132]  W^T chunk: [k][o]
    float* sB = dsm + 3 * STG_FLOATS;   // [3][16][132]  x chunk:   [k][s]

    const int b  = blockIdx.z;
    const int m0 = blockIdx.y * 128;    // o
    const int n0 = blockIdx.x * 128;    // s
    const int tid = threadIdx.x;
    const int wid = tid >> 5;
    const int wm = wid & 1;             // 0..1 -> o offset wm*64
    const int wn = wid >> 1;            // 0..3 -> s offset wn*32

    const float* xb = x + (size_t)b * CIN * SPATIAL;

    const int c0 = tid, c1 = tid + 256;
    const int kk0 = c0 >> 5, off0 = (c0 & 31) * 4;
    const int kk1 = c1 >> 5, off1 = (c1 & 31) * 4;

    wmma::fragment<wmma::accumulator, 16, 16, 8, float> acc[4][2];
#pragma unroll
    for (int i = 0; i < 4; i++)
#pragma unroll
        for (int j = 0; j < 2; j++) wmma::fill_fragment(acc[i][j], 0.f);

    auto load_stage = [&](int st, int t) {
        const int k0 = t * GBK;
        CP_ASYNC16(smem_u32(sA + (st * GBK + kk0) * ASTR + off0),
                   g_wt + (size_t)(k0 + kk0) * OQKV + m0 + off0);
        CP_ASYNC16(smem_u32(sA + (st * GBK + kk1) * ASTR + off1),
                   g_wt + (size_t)(k0 + kk1) * OQKV + m0 + off1);
        CP_ASYNC16(smem_u32(sB + (st * GBK + kk0) * ASTR + off0),
                   xb + (size_t)(k0 + kk0) * SPATIAL + n0 + off0);
        CP_ASYNC16(smem_u32(sB + (st * GBK + kk1) * ASTR + off1),
                   xb + (size_t)(k0 + kk1) * SPATIAL + n0 + off1);
    };

    load_stage(0, 0); CP_COMMIT();
    load_stage(1, 1); CP_COMMIT();

    for (int t = 0; t < NT; t++) {
        CP_WAIT1();
        __syncthreads();
        if (t + 2 < NT) load_stage((t + 2) % 3, t + 2);
        CP_COMMIT();
        const int st = t % 3;

#pragma unroll
        for (int kk = 0; kk < GBK; kk += 8) {
            wmma::fragment<wmma::matrix_a, 16, 16, 8, wmma::precision::tf32,
                           wmma::col_major> af[4], ah[4];
            wmma::fragment<wmma::matrix_b, 16, 16, 8, wmma::precision::tf32,
                           wmma::row_major> bf[2], bh[2];
            const float* abase = sA + (st * GBK + kk) * ASTR + wm * 64;
            const float* bbase = sB + (st * GBK + kk) * ASTR + wn * 32;
#pragma unroll
            for (int i = 0; i < 4; i++)
                wmma::load_matrix_sync(af[i], abase + i * 16, ASTR);
#pragma unroll
            for (int j = 0; j < 2; j++)
                wmma::load_matrix_sync(bf[j], bbase + j * 16, ASTR);

            // hi parts
#pragma unroll
            for (int i = 0; i < 4; i++)
#pragma unroll
                for (int e = 0; e < af[i].num_elements; e++)
                    ah[i].x[e] = wmma::__float_to_tf32(af[i].x[e]);
#pragma unroll
            for (int j = 0; j < 2; j++)
#pragma unroll
                for (int e = 0; e < bf[j].num_elements; e++)
                    bh[j].x[e] = wmma::__float_to_tf32(bf[j].x[e]);

            // acc += a_hi * b_hi
#pragma unroll
            for (int i = 0; i < 4; i++)
#pragma unroll
                for (int j = 0; j < 2; j++)
                    wmma::mma_sync(acc[i][j], ah[i], bh[j], acc[i][j]);

            // a_lo (overwrite af)
#pragma unroll
            for (int i = 0; i < 4; i++)
#pragma unroll
                for (int e = 0; e < af[i].num_elements; e++)
                    af[i].x[e] = wmma::__float_to_tf32(af[i].x[e] - ah[i].x[e]);
            // acc += a_lo * b_hi
#pragma unroll
            for (int i = 0; i < 4; i++)
#pragma unroll
                for (int j = 0; j < 2; j++)
                    wmma::mma_sync(acc[i][j], af[i], bh[j], acc[i][j]);

            // b_lo (overwrite bf)
#pragma unroll
            for (int j = 0; j < 2; j++)
#pragma unroll
                for (int e = 0; e < bf[j].num_elements; e++)
                    bf[j].x[e] = wmma::__float_to_tf32(bf[j].x[e] - bh[j].x[e]);
            // acc += a_hi * b_lo
#pragma unroll
            for (int i = 0; i < 4; i++)
#pragma unroll
                for (int j = 0; j < 2; j++)
                    wmma::mma_sync(acc[i][j], ah[i], bf[j], acc[i][j]);
        }
        __syncthreads();
    }

    // epilogue: 16x16 tiles straight into c-major g_qT / g_kvT (mem_col_major:
    // element (o,s) at ptr[o + s*ld]); a 16-row o-chunk never crosses a head.
#pragma unroll
    for (int i = 0; i < 4; i++) {
        const int o0 = m0 + wm * 64 + i * 16;
#pragma unroll
        for (int j = 0; j < 2; j++) {
            const int s0 = n0 + wn * 32 + j * 16;
            float* ptr;
            int ld;
            if (o0 < 256) {
                ptr = g_qT + ((size_t)(b * NUM_HEADS + (o0 >> 5)) * SPATIAL + s0) * DHEAD
                    + (o0 & 31);
                ld = DHEAD;
            } else {
                const int oo = o0 - 256;
                ptr = g_kvT + ((size_t)(b * NUM_HEADS + (oo >> 6)) * SPATIAL + s0) * 64
                    + (oo & 63);
                ld = 64;
            }
            wmma::store_matrix_sync(ptr, acc[i][j], ld, wmma::mem_col_major);
        }
    }
}

// ---------------- kernel 2: halo attention (round-12, locked) ----------------
#define KV_STRIDE 68
#define SMEM_KV   (WINP * KV_STRIDE)
#define RELSTRIDE 36
#define SMEM_REL  (27 * RELSTRIDE)
#define SMEM_FLOATS (SMEM_KV + 2 * SMEM_REL)
#define SMEM_BYTES  (SMEM_FLOATS * 4)

__global__ void __launch_bounds__(128) halo_attn(
    const float* __restrict__ hrel,
    const float* __restrict__ wrel,
    float* __restrict__ out)
{
    extern __shared__ float fsm[];
    float* sKV = fsm;
    float* sH  = fsm + SMEM_KV;
    float* sW  = sH + SMEM_REL;

    const int tid = threadIdx.x;
    const int nbidx = blockIdx.x;
    const int bh = blockIdx.y;
    const int b = bh >> 3, head = bh & 7;
    const int by = nbidx / NHB, bx = nbidx % NHB;

    for (int idx = tid; idx < 27 * 32; idx += 128) {
        const int r = idx >> 5, d = idx & 31;
        sH[r * RELSTRIDE + d] = hrel[idx];
        sW[r * RELSTRIDE + d] = wrel[idx];
    }

    const float* kvb = g_kvT + ((size_t)(b * NUM_HEADS + head)) * SPATIAL * 64;
#pragma unroll
    for (int rep = 0; rep < 2; rep++) {
        const int p = tid + rep * 128;
        if (p < WINP) {
            const int y = p / WIN, xx = p % WIN;
            const int gh = by * BLOCK_SZ + y - HALO;
            const int gw = bx * BLOCK_SZ + xx - HALO;
            float4* dst = (float4*)(sKV + p * KV_STRIDE);
            if (((unsigned)gh < (unsigned)HW) && ((unsigned)gw < (unsigned)HW)) {
                const float4* src = (const float4*)(kvb + (size_t)(gh * HW + gw) * 64);
#pragma unroll
                for (int c = 0; c < 16; c++) dst[c] = src[c];
            } else {
                const float4 z = make_float4(0.f, 0.f, 0.f, 0.f);
#pragma unroll
                for (int c = 0; c < 16; c++) dst[c] = z;
            }
        }
    }

    const int q    = tid >> 1;
    const int half = tid & 1;
    const int qi = q >> 3, qj = q & 7;
    const int sp = (by * BLOCK_SZ + qi) * HW + bx * BLOCK_SZ + qj;
    const ulonglong2* qp = (const ulonglong2*)(
        g_qT + (((size_t)(b * NUM_HEADS + head)) * SPATIAL + sp) * DHEAD);

    u64 q2[16];
    const u64 le2 = pack2(LOG2E, LOG2E);
#pragma unroll
    for (int mm = 0; mm < 8; mm++) {
        ulonglong2 qv = qp[mm];
        q2[2 * mm]     = qv.x;
        q2[2 * mm + 1] = qv.y;
    }
#pragma unroll
    for (int dd = 0; dd < 16; dd++) mul2(q2[dd], le2);

    __syncthreads();

    float rw[14];
#pragma unroll
    for (int xx = 0; xx < 14; xx++) {
        const ulonglong2* wr = (const ulonglong2*)&sW[(13 + xx - qj) * RELSTRIDE];
        u64 s0 = 0ULL, s1 = 0ULL;
#pragma unroll
        for (int m = 0; m < 8; m++) {
            ulonglong2 wv = wr[m];
            fma2(s0, q2[2 * m],     wv.x);
            fma2(s1, q2[2 * m + 1], wv.y);
        }
        float l0, h0; unpack2(add2(s0, s1), l0, h0);
        rw[xx] = l0 + h0;
    }
    const int y0 = half * 7;
    float rh[7];
#pragma unroll
    for (int yy = 0; yy < 7; yy++) {
        const ulonglong2* hr = (const ulonglong2*)&sH[(13 + y0 + yy - qi) * RELSTRIDE];
        u64 s0 = 0ULL, s1 = 0ULL;
#pragma unroll
        for (int m = 0; m < 8; m++) {
            ulonglong2 hv = hr[m];
            fma2(s0, q2[2 * m],     hv.x);
            fma2(s1, q2[2 * m + 1], hv.y);
        }
        float l0, h0; unpack2(add2(s0, s1), l0, h0);
        rh[yy] = l0 + h0;
    }
    const u64 sc2 = pack2(SCALE, SCALE);
#pragma unroll
    for (int dd = 0; dd < 16; dd++) mul2(q2[dd], sc2);

    float m = -1e30f, l = 0.f;
    u64 acc2[16];
#pragma unroll
    for (int dd = 0; dd < 16; dd++) acc2[dd] = 0ULL;

    for (int yy = 0; yy < 7; yy++) {
        const float* kvp = sKV + (y0 + yy) * WIN * KV_STRIDE;
        const float rhv = rh[yy];
        float lg[14];
#pragma unroll
        for (int xx = 0; xx < 14; xx++) {
            const ulonglong2* kp = (const ulonglong2*)(kvp + xx * KV_STRIDE);
            u64 s0 = 0ULL, s1 = 0ULL;
#pragma unroll
            for (int mm = 0; mm < 8; mm++) {
                ulonglong2 kv = kp[mm];
                fma2(s0, q2[2 * mm],     kv.x);
                fma2(s1, q2[2 * mm + 1], kv.y);
            }
            float l0, h0; unpack2(add2(s0, s1), l0, h0);
            lg[xx] = l0 + h0 + rhv + rw[xx];
        }
        float t0 = fmaxf(lg[0], lg[1]),  t1 = fmaxf(lg[2], lg[3]);
        float t2 = fmaxf(lg[4], lg[5]),  t3 = fmaxf(lg[6], lg[7]);
        float t4 = fmaxf(lg[8], lg[9]),  t5 = fmaxf(lg[10], lg[11]);
        float t6 = fmaxf(lg[12], lg[13]);
        t0 = fmaxf(t0, t1); t2 = fmaxf(t2, t3); t4 = fmaxf(t4, t5);
        const float rowm = fmaxf(fmaxf(t0, t2), fmaxf(t4, t6));

        const float mnew = fmaxf(m, rowm);
        const float corr = exp2f(m - mnew);
        m = mnew;

#pragma unroll
        for (int xx = 0; xx < 14; xx++) lg[xx] = exp2f(lg[xx] - mnew);

        float u0 = lg[0] + lg[1],   u1 = lg[2] + lg[3];
        float u2 = lg[4] + lg[5],   u3 = lg[6] + lg[7];
        float u4 = lg[8] + lg[9],   u5 = lg[10] + lg[11];
        float u6 = lg[12] + lg[13];
        l = l * corr + ((u0 + u1) + (u2 + u3)) + ((u4 + u5) + u6);

        const u64 c2 = pack2(corr, corr);
#pragma unroll
        for (int dd = 0; dd < 16; dd++) mul2(acc2[dd], c2);

#pragma unroll
        for (int xx = 0; xx < 14; xx++) {
            const u64 p2 = pack2(lg[xx], lg[xx]);
            const ulonglong2* vp = (const ulonglong2*)(kvp + xx * KV_STRIDE + 32);
#pragma unroll
            for (int mm = 0; mm < 8; mm++) {
                ulonglong2 vv = vp[mm];
                fma2(acc2[2 * mm],     p2, vv.x);
                fma2(acc2[2 * mm + 1], p2, vv.y);
            }
        }
    }

    const unsigned FULL = 0xFFFFFFFFu;
    const float m2 = __shfl_xor_sync(FULL, m, 1);
    const float M  = fmaxf(m, m2);
    const float w  = exp2f(m - M);
    const float lw = l * w;
    const float L  = lw + __shfl_xor_sync(FULL, lw, 1);
    const float inv = 1.0f / L;

    float* ob = out + ((size_t)b * 256 + head * DHEAD) * SPATIAL + sp;
#pragma unroll
    for (int dd = 0; dd < 16; dd++) {
        float f0, f1; unpack2(acc2[dd], f0, f1);
        f0 *= w; f1 *= w;
        f0 += __shfl_xor_sync(FULL, f0, 1);
        f1 += __shfl_xor_sync(FULL, f1, 1);
        if (half == 0) {
            ob[(size_t)(2 * dd) * SPATIAL]     = f0 * inv;
            ob[(size_t)(2 * dd + 1) * SPATIAL] = f1 * inv;
        }
    }
}

// ---------------- launch ----------------
extern "C" void kernel_launch(void* const* d_in, const int* in_sizes, int n_in,
                              void* d_out, int out_size)
{
    const float* x    = (const float*)d_in[0];
    const float* qw   = (const float*)d_in[1];
    const float* kvw  = (const float*)d_in[2];
    const float* hrel = (const float*)d_in[3];
    const float* wrel = (const float*)d_in[4];
    float* out = (float*)d_out;

    cudaFuncSetAttribute(qkv_gemm, cudaFuncAttributeMaxDynamicSharedMemorySize,
                         GEMM_SMEM);
    cudaFuncSetAttribute(halo_attn, cudaFuncAttributeMaxDynamicSharedMemorySize,
                         SMEM_BYTES);

    wt_kernel<<<dim3(OQKV / 32, CIN / 32), dim3(32, 32)>>>(qw, kvw);
    qkv_gemm<<<dim3(SPATIAL / 128, OQKV / 128, BATCH), 256, GEMM_SMEM>>>(x);
    halo_attn<<<dim3(NB, BATCH * NUM_HEADS), 128, SMEM_BYTES>>>(hrel, wrel, out);
}

// round 15
// speedup vs baseline: 1.3472x; 1.3472x over previous
#include <cuda_runtime.h>
#include <cstdint>
#include <cstddef>

// ---------------- problem constants ----------------
#define NUM_HEADS 8
#define DHEAD 32
#define BLOCK_SZ 8
#define HALO 3
#define WIN 14
#define WINP 196
#define NHB 12
#define NB 144
#define HW 96
#define SPATIAL 9216
#define BATCH 8
#define CIN 256
#define OQKV 768
#define SCALE 0.17677669529663687f
#define LOG2E 1.4426950408889634f

typedef unsigned long long u64;

// ---- f32x2 packed-math helpers ----
__device__ __forceinline__ u64 pack2(float lo, float hi) {
    u64 r; asm("mov.b64 %0, {%1, %2};" : "=l"(r) : "f"(lo), "f"(hi)); return r;
}
__device__ __forceinline__ void unpack2(u64 v, float& lo, float& hi) {
    asm("mov.b64 {%0, %1}, %2;" : "=f"(lo), "=f"(hi) : "l"(v));
}
__device__ __forceinline__ void fma2(u64& d, u64 a, u64 b) {
    asm("fma.rn.f32x2 %0, %1, %2, %0;" : "+l"(d) : "l"(a), "l"(b));
}
__device__ __forceinline__ void mul2(u64& d, u64 a) {
    asm("mul.rn.f32x2 %0, %0, %1;" : "+l"(d) : "l"(a));
}
__device__ __forceinline__ u64 add2(u64 a, u64 b) {
    u64 r; asm("add.rn.f32x2 %0, %1, %2;" : "=l"(r) : "l"(a), "l"(b)); return r;
}
__device__ __forceinline__ unsigned smem_u32(const void* p) {
    unsigned a;
    asm("{ .reg .u64 t; cvta.to.shared.u64 t, %1; cvt.u32.u64 %0, t; }"
        : "=r"(a) : "l"(p));
    return a;
}
#define CP_ASYNC16(dst_u32, src) \
    asm volatile("cp.async.cg.shared.global [%0], [%1], 16;" :: "r"(dst_u32), "l"(src))
#define CP_COMMIT() asm volatile("cp.async.commit_group;")
#define CP_WAIT1()  asm volatile("cp.async.wait_group 1;" ::: "memory")

// scratch — attention-friendly layouts
__device__ float g_wt[(size_t)CIN * OQKV];                              // W^T [k][o]
__device__ float g_qT[(size_t)BATCH * NUM_HEADS * SPATIAL * DHEAD];     // [b][h][s][32]
__device__ float g_kvT[(size_t)BATCH * NUM_HEADS * SPATIAL * 64];       // [b][h][s][64]

// ---------------- kernel 0: weight transpose ----------------
__global__ void __launch_bounds__(1024) wt_kernel(
    const float* __restrict__ qw, const float* __restrict__ kvw)
{
    __shared__ float t[32][33];
    const int o0 = blockIdx.x * 32;
    const int k0 = blockIdx.y * 32;
    const int o = o0 + threadIdx.y;
    const int k = k0 + threadIdx.x;
    const float* src = (o < 256) ? (qw + (size_t)o * CIN) : (kvw + (size_t)(o - 256) * CIN);
    t[threadIdx.y][threadIdx.x] = src[k];
    __syncthreads();
    g_wt[(size_t)(k0 + threadIdx.y) * OQKV + o0 + threadIdx.x] = t[threadIdx.x][threadIdx.y];
}

// ---------------- kernel 1: QKV GEMM — FFMA2, cp.async 3-stage, BK=32 --------
// C[o][s] = sum_k Wt[k][o] * x[b][k][s].  Tile 128(o) x 128(s), 256 threads,
// 8x8 micro-tile (tc owns o -> coalesced c-major epilogue), BK=32 (8 k-tiles,
// 8 syncthreads instead of 16).
#define GBK 32
#define NT  (CIN / GBK)                 // 8 tiles
#define STG (GBK * 132)                 // floats per stage per matrix
#define GEMM_SMEM (3 * 2 * STG * 4)     // 101376 B

__global__ void __launch_bounds__(256) qkv_gemm(const float* __restrict__ x)
{
    extern __shared__ float dsm[];
    float* sA = dsm;                    // [3][32][132]  W^T chunk: [k][o]
    float* sB = dsm + 3 * STG;          // [3][32][132]  x chunk:   [k][s]

    const int b  = blockIdx.z;
    const int m0 = blockIdx.y * 128;    // o
    const int n0 = blockIdx.x * 128;    // s
    const int tid = threadIdx.x;

    const float* xb = x + (size_t)b * CIN * SPATIAL;

    const int tr = tid >> 4;            // 0..15 : s-rows tr*8..+7
    const int tc = tid & 15;            // 0..15 : o-cols tc*8..+7

    // staging: 1024 16B-chunks per stage per matrix; 4 per thread
    int kk[4], off[4];
#pragma unroll
    for (int i = 0; i < 4; i++) {
        const int c = tid + i * 256;
        kk[i]  = c >> 5;
        off[i] = (c & 31) * 4;
    }

    u64 acc2[4][8];   // [o-pair i][s j]
#pragma unroll
    for (int i = 0; i < 4; i++)
#pragma unroll
        for (int j = 0; j < 8; j++) acc2[i][j] = 0ULL;

    auto load_stage = [&](int st, int t) {
        const int k0 = t * GBK;
#pragma unroll
        for (int i = 0; i < 4; i++) {
            CP_ASYNC16(smem_u32(sA + (st * GBK + kk[i]) * 132 + off[i]),
                       g_wt + (size_t)(k0 + kk[i]) * OQKV + m0 + off[i]);
            CP_ASYNC16(smem_u32(sB + (st * GBK + kk[i]) * 132 + off[i]),
                       xb + (size_t)(k0 + kk[i]) * SPATIAL + n0 + off[i]);
        }
    };

    load_stage(0, 0); CP_COMMIT();
    load_stage(1, 1); CP_COMMIT();

    for (int t = 0; t < NT; t++) {
        CP_WAIT1();
        __syncthreads();
        if (t + 2 < NT) load_stage((t + 2) % 3, t + 2);
        CP_COMMIT();
        const int st = t % 3;

#pragma unroll
        for (int k = 0; k < GBK; k++) {
            const float* arow = sA + (st * GBK + k) * 132;
            const float* brow = sB + (st * GBK + k) * 132;
            ulonglong2 a01 = *(const ulonglong2*)(arow + tc * 8);
            ulonglong2 a23 = *(const ulonglong2*)(arow + tc * 8 + 4);
            u64 a2[4] = {a01.x, a01.y, a23.x, a23.y};
            float4 b0 = *(const float4*)(brow + tr * 8);
            float4 b1 = *(const float4*)(brow + tr * 8 + 4);
            u64 bd[8];
            bd[0] = pack2(b0.x, b0.x); bd[1] = pack2(b0.y, b0.y);
            bd[2] = pack2(b0.z, b0.z); bd[3] = pack2(b0.w, b0.w);
            bd[4] = pack2(b1.x, b1.x); bd[5] = pack2(b1.y, b1.y);
            bd[6] = pack2(b1.z, b1.z); bd[7] = pack2(b1.w, b1.w);
#pragma unroll
            for (int i = 0; i < 4; i++)
#pragma unroll
                for (int j = 0; j < 8; j++)
                    fma2(acc2[i][j], a2[i], bd[j]);
        }
    }

    // epilogue: coalesced c-major writes (tc owns o)
    const int o = m0 + tc * 8;
    float* base;
    int cw;
    if (o < 256) {
        base = g_qT + (((size_t)b * NUM_HEADS + (o >> 5)) * SPATIAL) * DHEAD + (o & 31);
        cw = DHEAD;
    } else {
        const int oo = o - 256;
        base = g_kvT + (((size_t)b * NUM_HEADS + (oo >> 6)) * SPATIAL) * 64 + (oo & 63);
        cw = 64;
    }
#pragma unroll
    for (int j = 0; j < 8; j++) {
        float v[8];
#pragma unroll
        for (int i = 0; i < 4; i++) {
            float lo, hi; unpack2(acc2[i][j], lo, hi);
            v[2 * i] = lo; v[2 * i + 1] = hi;
        }
        const int s = n0 + tr * 8 + j;
        float* dst = base + (size_t)s * cw;
        *(float4*)(dst)     = make_float4(v[0], v[1], v[2], v[3]);
        *(float4*)(dst + 4) = make_float4(v[4], v[5], v[6], v[7]);
    }
}

// ---------------- kernel 2: halo attention (round-12, locked) ----------------
#define KV_STRIDE 68
#define SMEM_KV   (WINP * KV_STRIDE)
#define RELSTRIDE 36
#define SMEM_REL  (27 * RELSTRIDE)
#define SMEM_FLOATS (SMEM_KV + 2 * SMEM_REL)
#define SMEM_BYTES  (SMEM_FLOATS * 4)

__global__ void __launch_bounds__(128) halo_attn(
    const float* __restrict__ hrel,
    const float* __restrict__ wrel,
    float* __restrict__ out)
{
    extern __shared__ float fsm[];
    float* sKV = fsm;
    float* sH  = fsm + SMEM_KV;
    float* sW  = sH + SMEM_REL;

    const int tid = threadIdx.x;
    const int nbidx = blockIdx.x;
    const int bh = blockIdx.y;
    const int b = bh >> 3, head = bh & 7;
    const int by = nbidx / NHB, bx = nbidx % NHB;

    for (int idx = tid; idx < 27 * 32; idx += 128) {
        const int r = idx >> 5, d = idx & 31;
        sH[r * RELSTRIDE + d] = hrel[idx];
        sW[r * RELSTRIDE + d] = wrel[idx];
    }

    const float* kvb = g_kvT + ((size_t)(b * NUM_HEADS + head)) * SPATIAL * 64;
#pragma unroll
    for (int rep = 0; rep < 2; rep++) {
        const int p = tid + rep * 128;
        if (p < WINP) {
            const int y = p / WIN, xx = p % WIN;
            const int gh = by * BLOCK_SZ + y - HALO;
            const int gw = bx * BLOCK_SZ + xx - HALO;
            float4* dst = (float4*)(sKV + p * KV_STRIDE);
            if (((unsigned)gh < (unsigned)HW) && ((unsigned)gw < (unsigned)HW)) {
                const float4* src = (const float4*)(kvb + (size_t)(gh * HW + gw) * 64);
#pragma unroll
                for (int c = 0; c < 16; c++) dst[c] = src[c];
            } else {
                const float4 z = make_float4(0.f, 0.f, 0.f, 0.f);
#pragma unroll
                for (int c = 0; c < 16; c++) dst[c] = z;
            }
        }
    }

    const int q    = tid >> 1;
    const int half = tid & 1;
    const int qi = q >> 3, qj = q & 7;
    const int sp = (by * BLOCK_SZ + qi) * HW + bx * BLOCK_SZ + qj;
    const ulonglong2* qp = (const ulonglong2*)(
        g_qT + (((size_t)(b * NUM_HEADS + head)) * SPATIAL + sp) * DHEAD);

    u64 q2[16];
    const u64 le2 = pack2(LOG2E, LOG2E);
#pragma unroll
    for (int mm = 0; mm < 8; mm++) {
        ulonglong2 qv = qp[mm];
        q2[2 * mm]     = qv.x;
        q2[2 * mm + 1] = qv.y;
    }
#pragma unroll
    for (int dd = 0; dd < 16; dd++) mul2(q2[dd], le2);

    __syncthreads();

    float rw[14];
#pragma unroll
    for (int xx = 0; xx < 14; xx++) {
        const ulonglong2* wr = (const ulonglong2*)&sW[(13 + xx - qj) * RELSTRIDE];
        u64 s0 = 0ULL, s1 = 0ULL;
#pragma unroll
        for (int m = 0; m < 8; m++) {
            ulonglong2 wv = wr[m];
            fma2(s0, q2[2 * m],     wv.x);
            fma2(s1, q2[2 * m + 1], wv.y);
        }
        float l0, h0; unpack2(add2(s0, s1), l0, h0);
        rw[xx] = l0 + h0;
    }
    const int y0 = half * 7;
    float rh[7];
#pragma unroll
    for (int yy = 0; yy < 7; yy++) {
        const ulonglong2* hr = (const ulonglong2*)&sH[(13 + y0 + yy - qi) * RELSTRIDE];
        u64 s0 = 0ULL, s1 = 0ULL;
#pragma unroll
        for (int m = 0; m < 8; m++) {
            ulonglong2 hv = hr[m];
            fma2(s0, q2[2 * m],     hv.x);
            fma2(s1, q2[2 * m + 1], hv.y);
        }
        float l0, h0; unpack2(add2(s0, s1), l0, h0);
        rh[yy] = l0 + h0;
    }
    const u64 sc2 = pack2(SCALE, SCALE);
#pragma unroll
    for (int dd = 0; dd < 16; dd++) mul2(q2[dd], sc2);

    float m = -1e30f, l = 0.f;
    u64 acc2[16];
#pragma unroll
    for (int dd = 0; dd < 16; dd++) acc2[dd] = 0ULL;

    for (int yy = 0; yy < 7; yy++) {
        const float* kvp = sKV + (y0 + yy) * WIN * KV_STRIDE;
        const float rhv = rh[yy];
        float lg[14];
#pragma unroll
        for (int xx = 0; xx < 14; xx++) {
            const ulonglong2* kp = (const ulonglong2*)(kvp + xx * KV_STRIDE);
            u64 s0 = 0ULL, s1 = 0ULL;
#pragma unroll
            for (int mm = 0; mm < 8; mm++) {
                ulonglong2 kv = kp[mm];
                fma2(s0, q2[2 * mm],     kv.x);
                fma2(s1, q2[2 * mm + 1], kv.y);
            }
            float l0, h0; unpack2(add2(s0, s1), l0, h0);
            lg[xx] = l0 + h0 + rhv + rw[xx];
        }
        float t0 = fmaxf(lg[0], lg[1]),  t1 = fmaxf(lg[2], lg[3]);
        float t2 = fmaxf(lg[4], lg[5]),  t3 = fmaxf(lg[6], lg[7]);
        float t4 = fmaxf(lg[8], lg[9]),  t5 = fmaxf(lg[10], lg[11]);
        float t6 = fmaxf(lg[12], lg[13]);
        t0 = fmaxf(t0, t1); t2 = fmaxf(t2, t3); t4 = fmaxf(t4, t5);
        const float rowm = fmaxf(fmaxf(t0, t2), fmaxf(t4, t6));

        const float mnew = fmaxf(m, rowm);
        const float corr = exp2f(m - mnew);
        m = mnew;

#pragma unroll
        for (int xx = 0; xx < 14; xx++) lg[xx] = exp2f(lg[xx] - mnew);

        float u0 = lg[0] + lg[1],   u1 = lg[2] + lg[3];
        float u2 = lg[4] + lg[5],   u3 = lg[6] + lg[7];
        float u4 = lg[8] + lg[9],   u5 = lg[10] + lg[11];
        float u6 = lg[12] + lg[13];
        l = l * corr + ((u0 + u1) + (u2 + u3)) + ((u4 + u5) + u6);

        const u64 c2 = pack2(corr, corr);
#pragma unroll
        for (int dd = 0; dd < 16; dd++) mul2(acc2[dd], c2);

#pragma unroll
        for (int xx = 0; xx < 14; xx++) {
            const u64 p2 = pack2(lg[xx], lg[xx]);
            const ulonglong2* vp = (const ulonglong2*)(kvp + xx * KV_STRIDE + 32);
#pragma unroll
            for (int mm = 0; mm < 8; mm++) {
                ulonglong2 vv = vp[mm];
                fma2(acc2[2 * mm],     p2, vv.x);
                fma2(acc2[2 * mm + 1], p2, vv.y);
            }
        }
    }

    const unsigned FULL = 0xFFFFFFFFu;
    const float m2 = __shfl_xor_sync(FULL, m, 1);
    const float M  = fmaxf(m, m2);
    const float w  = exp2f(m - M);
    const float lw = l * w;
    const float L  = lw + __shfl_xor_sync(FULL, lw, 1);
    const float inv = 1.0f / L;

    float* ob = out + ((size_t)b * 256 + head * DHEAD) * SPATIAL + sp;
#pragma unroll
    for (int dd = 0; dd < 16; dd++) {
        float f0, f1; unpack2(acc2[dd], f0, f1);
        f0 *= w; f1 *= w;
        f0 += __shfl_xor_sync(FULL, f0, 1);
        f1 += __shfl_xor_sync(FULL, f1, 1);
        if (half == 0) {
            ob[(size_t)(2 * dd) * SPATIAL]     = f0 * inv;
            ob[(size_t)(2 * dd + 1) * SPATIAL] = f1 * inv;
        }
    }
}

// ---------------- launch ----------------
extern "C" void kernel_launch(void* const* d_in, const int* in_sizes, int n_in,
                              void* d_out, int out_size)
{
    const float* x    = (const float*)d_in[0];
    const float* qw   = (const float*)d_in[1];
    const float* kvw  = (const float*)d_in[2];
    const float* hrel = (const float*)d_in[3];
    const float* wrel = (const float*)d_in[4];
    float* out = (float*)d_out;

    cudaFuncSetAttribute(qkv_gemm, cudaFuncAttributeMaxDynamicSharedMemorySize,
                         GEMM_SMEM);
    cudaFuncSetAttribute(halo_attn, cudaFuncAttributeMaxDynamicSharedMemorySize,
                         SMEM_BYTES);

    wt_kernel<<<dim3(OQKV / 32, CIN / 32), dim3(32, 32)>>>(qw, kvw);
    qkv_gemm<<<dim3(SPATIAL / 128, OQKV / 128, BATCH), 256, GEMM_SMEM>>>(x);
    halo_attn<<<dim3(NB, BATCH * NUM_HEADS), 128, SMEM_BYTES>>>(hrel, wrel, out);
}